// round 15
// baseline (speedup 1.0000x reference)
#include <cuda_runtime.h>
#include <cuda_fp16.h>
#include <cstdint>

#define FULLMASK 0xffffffffu

// ---------------------------------------------------------------------------
// Device-global scratch (allocation-free rule). All fp16.
static __device__ __half g_Ah[4096 * 3072];   // concat [q|k|v]
static __device__ __half g_Wh[3072 * 3072];   // W_qkv
static __device__ __half g_Wph[1024 * 1024];  // W_proj
static __device__ __half g_Q[32 * 2048 * 64]; // [B*H, N, hd], scale*log2e folded
static __device__ __half g_K[32 * 2048 * 64];
static __device__ __half g_V[32 * 2048 * 64];
static __device__ __half g_Xh[2 * 2048 * 1024];

__device__ __forceinline__ uint32_t smem_u32(const void* p) {
    uint32_t a;
    asm("{ .reg .u64 t; cvta.to.shared.u64 t, %1; cvt.u32.u64 %0, t; }"
        : "=r"(a) : "l"(p));
    return a;
}

#define CP_ASYNC16(dst, src) \
    asm volatile("cp.async.cg.shared.global [%0], [%1], 16;" :: "r"(dst), "l"(src))
#define CP_COMMIT() asm volatile("cp.async.commit_group;" ::: "memory")
#define CP_WAIT1()  asm volatile("cp.async.wait_group 1;"  ::: "memory")
#define CP_WAIT0()  asm volatile("cp.async.wait_group 0;"  ::: "memory")

#define LDSM_X4(r0, r1, r2, r3, addr) \
    asm volatile("ldmatrix.sync.aligned.m8n8.x4.shared.b16 {%0,%1,%2,%3}, [%4];" \
                 : "=r"(r0), "=r"(r1), "=r"(r2), "=r"(r3) : "r"(addr))

#define LDSM_X4_TRANS(r0, r1, r2, r3, addr) \
    asm volatile("ldmatrix.sync.aligned.m8n8.x4.trans.shared.b16 {%0,%1,%2,%3}, [%4];" \
                 : "=r"(r0), "=r"(r1), "=r"(r2), "=r"(r3) : "r"(addr))

__device__ __forceinline__ void mma16(float c[4], const uint32_t a[4], const uint32_t b[2]) {
    asm volatile(
        "mma.sync.aligned.m16n8k16.row.col.f32.f16.f16.f32 "
        "{%0,%1,%2,%3}, {%4,%5,%6,%7}, {%8,%9}, {%0,%1,%2,%3};"
        : "+f"(c[0]), "+f"(c[1]), "+f"(c[2]), "+f"(c[3])
        : "r"(a[0]), "r"(a[1]), "r"(a[2]), "r"(a[3]), "r"(b[0]), "r"(b[1]));
}

__device__ __forceinline__ uint32_t pack_h2(float lo, float hi) {
    __half2 h = __floats2half2_rn(lo, hi);
    return *reinterpret_cast<uint32_t*>(&h);
}

// exp2 on a packed f16x2 (single MUFU-class op for two values).
#define EX2_H2(r) asm("ex2.approx.f16x2 %0, %0;" : "+r"(r))

// Convert 8 fp32 (two float4) -> one uint4 of 8 fp16.
__device__ __forceinline__ uint4 cvt8(const float4 f0, const float4 f1) {
    uint4 o;
    o.x = pack_h2(f0.x, f0.y);
    o.y = pack_h2(f0.z, f0.w);
    o.z = pack_h2(f1.x, f1.y);
    o.w = pack_h2(f1.z, f1.w);
    return o;
}

// ---------------------------------------------------------------------------
// Prepass, vectorized: 8 elements per iteration, single 16B store.
// ---------------------------------------------------------------------------
__global__ void cvt_all(const float* __restrict__ q, const float* __restrict__ k,
                        const float* __restrict__ v, const float* __restrict__ Wqkv,
                        const float* __restrict__ Wp) {
    const int step = gridDim.x * blockDim.x * 8;
    const int tid0 = (blockIdx.x * blockDim.x + threadIdx.x) * 8;

    // A concat: c is a multiple of 8, slabs are 1024-wide -> 8-run stays in-slab.
    for (int i = tid0; i < 4096 * 3072; i += step) {
        const int r = i / 3072;
        const int c = i - r * 3072;
        const float* s = ((c < 1024) ? q : ((c < 2048) ? k : v)) + (size_t)r * 1024 + (c & 1023);
        const float4 f0 = ((const float4*)s)[0];
        const float4 f1 = ((const float4*)s)[1];
        *(uint4*)&g_Ah[i] = cvt8(f0, f1);
    }
    for (int i = tid0; i < 3072 * 3072; i += step) {
        const float4 f0 = *(const float4*)(Wqkv + i);
        const float4 f1 = *(const float4*)(Wqkv + i + 4);
        *(uint4*)&g_Wh[i] = cvt8(f0, f1);
    }
    for (int i = tid0; i < 1024 * 1024; i += step) {
        const float4 f0 = *(const float4*)(Wp + i);
        const float4 f1 = *(const float4*)(Wp + i + 4);
        *(uint4*)&g_Wph[i] = cvt8(f0, f1);
    }
}

// ---------------------------------------------------------------------------
// fp16 NT GEMM (best measured config): BK=64, 3-stage cp.async pipeline.
// Block 128x128, 256 threads (8 warps 4m x 2n), warp tile 32x64.
// Rows padded to 72 halfs (144B): LDSM + cp.async conflict-free.
// MODE 0: A=g_Ah, B=g_Wh, scatter fp16 to g_Q/g_K/g_V (Q scaled by 0.125*log2e).
// MODE 1: A=g_Xh, B=g_Wph, out = C + bias (fp32).
// ---------------------------------------------------------------------------
template <int MODE>
__global__ void __launch_bounds__(256, 2) gemm_h(const float* __restrict__ bias,
                                                 float* __restrict__ out)
{
    constexpr int KDIM = (MODE == 0) ? 3072 : 1024;
    constexpr int NK   = KDIM / 64;
    constexpr int TILE_BYTES  = 128 * 144;        // 18432 per matrix
    constexpr int STAGE_BYTES = 2 * TILE_BYTES;   // 36864

    extern __shared__ __align__(16) char sm[];
    const uint32_t sbase = smem_u32(sm);

    const __half* __restrict__ A = (MODE == 0) ? g_Ah : g_Xh;
    const __half* __restrict__ B = (MODE == 0) ? g_Wh : g_Wph;

    const int tid  = threadIdx.x;
    const int lane = tid & 31;
    const int w    = tid >> 5;
    const int gid  = lane >> 2;
    const int tig  = lane & 3;
    const int warp_m = (w >> 1) * 32;
    const int warp_n = (w & 1) * 64;
    const int mBase  = blockIdx.y * 128;
    const int nBase  = blockIdx.x * 128;

    const int row_in = lane & 7;
    const int sel    = lane >> 3;
    const int a_row_off = (sel & 1) * 8 + row_in;
    const int a_k_off   = (sel >> 1) * 8;
    const int b_row_off = (sel >> 1) * 8 + row_in;
    const int b_k_off   = (sel & 1) * 8;

    auto stage = [&](int kt, int st) {
#pragma unroll
        for (int i = 0; i < 8; i++) {
            const int c   = tid + 256 * i;       // 0..2047
            const int mat = c >> 10;             // 0=A, 1=B
            const int cc  = c & 1023;
            const int row = cc >> 3;
            const int ch  = cc & 7;
            const __half* src = (mat == 0)
                ? (A + (size_t)(mBase + row) * KDIM + kt * 64 + ch * 8)
                : (B + (size_t)(nBase + row) * KDIM + kt * 64 + ch * 8);
            const uint32_t dst = sbase + st * STAGE_BYTES + mat * TILE_BYTES
                               + row * 144 + ch * 16;
            CP_ASYNC16(dst, src);
        }
        CP_COMMIT();
    };

    float acc[2][8][4];
#pragma unroll
    for (int i = 0; i < 2; i++)
#pragma unroll
        for (int j = 0; j < 8; j++)
#pragma unroll
            for (int e = 0; e < 4; e++) acc[i][j][e] = 0.f;

    stage(0, 0);
    stage(1, 1);

    for (int kt = 0; kt < NK; kt++) {
        const int st = kt % 3;
        if (kt + 1 < NK) { CP_WAIT1(); } else { CP_WAIT0(); }
        __syncthreads();
        if (kt + 2 < NK) stage(kt + 2, (kt + 2) % 3);

        const uint32_t a_sm = sbase + st * STAGE_BYTES;
        const uint32_t b_sm = a_sm + TILE_BYTES;

#pragma unroll
        for (int ks = 0; ks < 4; ks++) {
            uint32_t a[2][4], b[8][2];
#pragma unroll
            for (int mt = 0; mt < 2; mt++) {
                const uint32_t addr = a_sm +
                    (warp_m + mt * 16 + a_row_off) * 144 + (ks * 16 + a_k_off) * 2;
                LDSM_X4(a[mt][0], a[mt][1], a[mt][2], a[mt][3], addr);
            }
#pragma unroll
            for (int pr = 0; pr < 4; pr++) {
                const uint32_t addr = b_sm +
                    (warp_n + pr * 16 + b_row_off) * 144 + (ks * 16 + b_k_off) * 2;
                LDSM_X4(b[2 * pr][0], b[2 * pr][1], b[2 * pr + 1][0], b[2 * pr + 1][1], addr);
            }
#pragma unroll
            for (int mt = 0; mt < 2; mt++)
#pragma unroll
                for (int nt = 0; nt < 8; nt++)
                    mma16(acc[mt][nt], a[mt], b[nt]);
        }
    }

    // Epilogue. C frag: c0(row g, col 2t), c1(g, 2t+1), c2(g+8, 2t), c3(g+8, 2t+1).
#pragma unroll
    for (int mt = 0; mt < 2; mt++) {
        const int row0 = mBase + warp_m + mt * 16 + gid;
#pragma unroll
        for (int nt = 0; nt < 8; nt++) {
            const int col = nBase + warp_n + nt * 8 + 2 * tig;
            if (MODE == 0) {
                const int t = col >> 10, hh = (col >> 6) & 15, d = col & 63;
                // Q pre-scale folds softmax scale AND log2(e) for exp2-softmax.
                const float sc = (t == 0) ? 0.125f * 1.44269504f : 1.f;
                __half* dst = ((t == 0) ? g_Q : ((t == 1) ? g_K : g_V)) +
                    ((size_t)((row0 >> 11) * 16 + hh) * 2048 + (row0 & 2047)) * 64 + d;
                *(__half2*)dst =
                    __floats2half2_rn(acc[mt][nt][0] * sc, acc[mt][nt][1] * sc);
                *(__half2*)(dst + 8 * 64) =
                    __floats2half2_rn(acc[mt][nt][2] * sc, acc[mt][nt][3] * sc);
            } else {
                const float b0 = bias[col], b1 = bias[col + 1];
                *(float2*)(out + (size_t)row0 * 1024 + col) =
                    make_float2(acc[mt][nt][0] + b0, acc[mt][nt][1] + b1);
                *(float2*)(out + (size_t)(row0 + 8) * 1024 + col) =
                    make_float2(acc[mt][nt][2] + b0, acc[mt][nt][3] + b1);
            }
        }
    }
}

// ---------------------------------------------------------------------------
// fp16 flash attention, fp16x2 exp2 + tensor-pipe denominator (ones-MMA).
// grid (16, 32), 256 threads, 3-stage cp.async.
// ---------------------------------------------------------------------------
__global__ void __launch_bounds__(256, 2) attn_flash_h()
{
    constexpr int KV_BYTES = 9216;       // 64 rows x 72 halfs (144B)
    constexpr int STAGE_BYTES = 2 * KV_BYTES;
    extern __shared__ __align__(16) char sm[];
    const uint32_t sbase = smem_u32(sm);

    const int bh    = blockIdx.y;
    const int qbase = blockIdx.x * 128;
    const int tid   = threadIdx.x;
    const int lane  = tid & 31;
    const int w     = tid >> 5;
    const int gid   = lane >> 2;
    const int tig   = lane & 3;

    const int row_in = lane & 7;
    const int sel    = lane >> 3;
    const int b_row_off = (sel >> 1) * 8 + row_in;
    const int b_k_off   = (sel & 1) * 8;
    const int v_krow_off = (sel & 1) * 8 + row_in;
    const int v_ncol_off = (sel >> 1) * 16;

    const __half* Kp = g_K + (size_t)bh * (2048 * 64);
    const __half* Vp = g_V + (size_t)bh * (2048 * 64);

    auto stage = [&](int kv_tile, int st) {
#pragma unroll
        for (int i = 0; i < 4; i++) {
            const int c   = tid + 256 * i;
            const int mat = c >> 9;          // 0=K, 1=V
            const int cc  = c & 511;
            const int row = cc >> 3;
            const int ch  = cc & 7;
            const __half* src = ((mat == 0) ? Kp : Vp) +
                (size_t)(kv_tile * 64 + row) * 64 + ch * 8;
            const uint32_t dst = sbase + st * STAGE_BYTES + mat * KV_BYTES + row * 144 + ch * 16;
            CP_ASYNC16(dst, src);
        }
        CP_COMMIT();
    };

    uint32_t qa[4][4];
    {
        const __half* q0 = g_Q + ((size_t)bh * 2048 + qbase + w * 16 + gid) * 64;
#pragma unroll
        for (int s = 0; s < 4; s++) {
            qa[s][0] = *(const uint32_t*)(q0 + s * 16 + 2 * tig);
            qa[s][1] = *(const uint32_t*)(q0 + 8 * 64 + s * 16 + 2 * tig);
            qa[s][2] = *(const uint32_t*)(q0 + s * 16 + 2 * tig + 8);
            qa[s][3] = *(const uint32_t*)(q0 + 8 * 64 + s * 16 + 2 * tig + 8);
        }
    }

    float o[8][4];
#pragma unroll
    for (int i = 0; i < 8; i++)
#pragma unroll
        for (int j = 0; j < 4; j++) o[i][j] = 0.f;

    // Denominator accumulator via ones-MMA: c0/c1 = row gid sum, c2/c3 = row gid+8.
    float l_acc[4] = {0.f, 0.f, 0.f, 0.f};
    const uint32_t ones2 = pack_h2(1.f, 1.f);
    const uint32_t ones_b[2] = {ones2, ones2};

    stage(0, 0);
    stage(1, 1);

    for (int it = 0; it < 32; it++) {
        const int st = it % 3;
        if (it + 1 < 32) { CP_WAIT1(); } else { CP_WAIT0(); }
        __syncthreads();
        if (it + 2 < 32) stage(it + 2, (it + 2) % 3);

        const uint32_t ksb = sbase + st * STAGE_BYTES;
        const uint32_t vsb = ksb + KV_BYTES;

        // S = Q K^T (base-2 domain: log2e pre-folded into Q)
        float s[8][4];
#pragma unroll
        for (int i = 0; i < 8; i++)
#pragma unroll
            for (int j = 0; j < 4; j++) s[i][j] = 0.f;
#pragma unroll
        for (int ks = 0; ks < 4; ks++) {
            uint32_t b[8][2];
#pragma unroll
            for (int pr = 0; pr < 4; pr++) {
                const uint32_t addr = ksb +
                    (pr * 16 + b_row_off) * 144 + (ks * 16 + b_k_off) * 2;
                LDSM_X4(b[2 * pr][0], b[2 * pr][1], b[2 * pr + 1][0], b[2 * pr + 1][1], addr);
            }
#pragma unroll
            for (int nt = 0; nt < 8; nt++)
                mma16(s[nt], qa[ks], b[nt]);
        }

        // P = exp2(S) in fp16x2; l via ones-MMA; O += P V.
#pragma unroll
        for (int kt = 0; kt < 4; kt++) {
            uint32_t pa[4];
            pa[0] = pack_h2(s[2 * kt][0],     s[2 * kt][1]);
            pa[1] = pack_h2(s[2 * kt][2],     s[2 * kt][3]);
            pa[2] = pack_h2(s[2 * kt + 1][0], s[2 * kt + 1][1]);
            pa[3] = pack_h2(s[2 * kt + 1][2], s[2 * kt + 1][3]);
            EX2_H2(pa[0]);
            EX2_H2(pa[1]);
            EX2_H2(pa[2]);
            EX2_H2(pa[3]);

            mma16(l_acc, pa, ones_b);   // row sums on the tensor pipe

#pragma unroll
            for (int pr = 0; pr < 4; pr++) {
                const uint32_t addr = vsb +
                    (kt * 16 + v_krow_off) * 144 + pr * 32 + v_ncol_off;
                uint32_t b[4];
                LDSM_X4_TRANS(b[0], b[1], b[2], b[3], addr);
                mma16(o[2 * pr],     pa, b);
                mma16(o[2 * pr + 1], pa, b + 2);
            }
        }
    }

    // l_acc already holds full row sums in every lane (ones-MMA reduces k).
    const float inv0 = 1.f / l_acc[0], inv1 = 1.f / l_acc[2];
    const int b = bh >> 4, h = bh & 15;
    const int n0 = qbase + w * 16 + gid;
    __half* x0 = g_Xh + ((size_t)b * 2048 + n0) * 1024 + h * 64;
    __half* x8 = x0 + 8 * 1024;
#pragma unroll
    for (int nt = 0; nt < 8; nt++) {
        const int d = nt * 8 + 2 * tig;
        *(__half2*)(x0 + d) = __floats2half2_rn(o[nt][0] * inv0, o[nt][1] * inv0);
        *(__half2*)(x8 + d) = __floats2half2_rn(o[nt][2] * inv1, o[nt][3] * inv1);
    }
}

// ---------------------------------------------------------------------------
extern "C" void kernel_launch(void* const* d_in, const int* in_sizes, int n_in,
                              void* d_out, int out_size)
{
    const float* q     = (const float*)d_in[0];
    const float* k     = (const float*)d_in[1];
    const float* v     = (const float*)d_in[2];
    const float* Wqkv  = (const float*)d_in[3];
    const float* Wproj = (const float*)d_in[4];
    const float* bproj = (const float*)d_in[5];
    float* out = (float*)d_out;

    static bool attr_done = false;
    const int GEMM_SMEM = 3 * 36864;   // 110592 (3-stage, BK=64); 2 CTAs = 221KB
    const int ATTN_SMEM = 3 * 18432;   // 55296
    if (!attr_done) {
        cudaFuncSetAttribute(gemm_h<0>, cudaFuncAttributeMaxDynamicSharedMemorySize, GEMM_SMEM);
        cudaFuncSetAttribute(gemm_h<1>, cudaFuncAttributeMaxDynamicSharedMemorySize, GEMM_SMEM);
        cudaFuncSetAttribute(attn_flash_h, cudaFuncAttributeMaxDynamicSharedMemorySize, ATTN_SMEM);
        attr_done = true;
    }

    // 0) merged, vectorized fp32 -> fp16 prepass
    cvt_all<<<2048, 256>>>(q, k, v, Wqkv, Wproj);
    // 1) fused QKV projection -> g_Q/g_K/g_V (fp16, Q pre-scaled incl. log2e)
    gemm_h<0><<<dim3(24, 32), 256, GEMM_SMEM>>>(nullptr, nullptr);
    // 2) flash attention -> g_Xh (fp16)
    attn_flash_h<<<dim3(16, 32), 256, ATTN_SMEM>>>();
    // 3) output projection + bias -> d_out (fp32)
    gemm_h<1><<<dim3(8, 32), 256, GEMM_SMEM>>>(bproj, out);
}

// round 16
// speedup vs baseline: 1.1121x; 1.1121x over previous
#include <cuda_runtime.h>
#include <cuda_fp16.h>
#include <cstdint>

#define FULLMASK 0xffffffffu

// ---------------------------------------------------------------------------
// Device-global scratch (allocation-free rule). All fp16.
static __device__ __half g_Ah[4096 * 3072];   // concat [q|k|v]
static __device__ __half g_Wh[3072 * 3072];   // W_qkv
static __device__ __half g_Wph[1024 * 1024];  // W_proj
static __device__ __half g_Q[32 * 2048 * 64]; // [B*H, N, hd], scale*log2e folded
static __device__ __half g_K[32 * 2048 * 64];
static __device__ __half g_V[32 * 2048 * 64];
static __device__ __half g_Xh[2 * 2048 * 1024];

__device__ __forceinline__ uint32_t smem_u32(const void* p) {
    uint32_t a;
    asm("{ .reg .u64 t; cvta.to.shared.u64 t, %1; cvt.u32.u64 %0, t; }"
        : "=r"(a) : "l"(p));
    return a;
}

#define CP_ASYNC16(dst, src) \
    asm volatile("cp.async.cg.shared.global [%0], [%1], 16;" :: "r"(dst), "l"(src))
#define CP_COMMIT() asm volatile("cp.async.commit_group;" ::: "memory")
#define CP_WAIT1()  asm volatile("cp.async.wait_group 1;"  ::: "memory")
#define CP_WAIT0()  asm volatile("cp.async.wait_group 0;"  ::: "memory")

#define LDSM_X4(r0, r1, r2, r3, addr) \
    asm volatile("ldmatrix.sync.aligned.m8n8.x4.shared.b16 {%0,%1,%2,%3}, [%4];" \
                 : "=r"(r0), "=r"(r1), "=r"(r2), "=r"(r3) : "r"(addr))

#define LDSM_X4_TRANS(r0, r1, r2, r3, addr) \
    asm volatile("ldmatrix.sync.aligned.m8n8.x4.trans.shared.b16 {%0,%1,%2,%3}, [%4];" \
                 : "=r"(r0), "=r"(r1), "=r"(r2), "=r"(r3) : "r"(addr))

__device__ __forceinline__ void mma16(float c[4], const uint32_t a[4], const uint32_t b[2]) {
    asm volatile(
        "mma.sync.aligned.m16n8k16.row.col.f32.f16.f16.f32 "
        "{%0,%1,%2,%3}, {%4,%5,%6,%7}, {%8,%9}, {%0,%1,%2,%3};"
        : "+f"(c[0]), "+f"(c[1]), "+f"(c[2]), "+f"(c[3])
        : "r"(a[0]), "r"(a[1]), "r"(a[2]), "r"(a[3]), "r"(b[0]), "r"(b[1]));
}

__device__ __forceinline__ uint32_t pack_h2(float lo, float hi) {
    __half2 h = __floats2half2_rn(lo, hi);
    return *reinterpret_cast<uint32_t*>(&h);
}

// exp2 on a packed f16x2 (single MUFU-class op for two values).
#define EX2_H2(r) asm("ex2.approx.f16x2 %0, %0;" : "+r"(r))

// Convert 8 fp32 (two float4) -> one uint4 of 8 fp16.
__device__ __forceinline__ uint4 cvt8(const float4 f0, const float4 f1) {
    uint4 o;
    o.x = pack_h2(f0.x, f0.y);
    o.y = pack_h2(f0.z, f0.w);
    o.z = pack_h2(f1.x, f1.y);
    o.w = pack_h2(f1.z, f1.w);
    return o;
}

// ---------------------------------------------------------------------------
// Prepass, vectorized: 8 elements per iteration, single 16B store.
// ---------------------------------------------------------------------------
__global__ void cvt_all(const float* __restrict__ q, const float* __restrict__ k,
                        const float* __restrict__ v, const float* __restrict__ Wqkv,
                        const float* __restrict__ Wp) {
    const int step = gridDim.x * blockDim.x * 8;
    const int tid0 = (blockIdx.x * blockDim.x + threadIdx.x) * 8;

    for (int i = tid0; i < 4096 * 3072; i += step) {
        const int r = i / 3072;
        const int c = i - r * 3072;
        const float* s = ((c < 1024) ? q : ((c < 2048) ? k : v)) + (size_t)r * 1024 + (c & 1023);
        const float4 f0 = ((const float4*)s)[0];
        const float4 f1 = ((const float4*)s)[1];
        *(uint4*)&g_Ah[i] = cvt8(f0, f1);
    }
    for (int i = tid0; i < 3072 * 3072; i += step) {
        const float4 f0 = *(const float4*)(Wqkv + i);
        const float4 f1 = *(const float4*)(Wqkv + i + 4);
        *(uint4*)&g_Wh[i] = cvt8(f0, f1);
    }
    for (int i = tid0; i < 1024 * 1024; i += step) {
        const float4 f0 = *(const float4*)(Wp + i);
        const float4 f1 = *(const float4*)(Wp + i + 4);
        *(uint4*)&g_Wph[i] = cvt8(f0, f1);
    }
}

// ---------------------------------------------------------------------------
// fp16 NT GEMM: BK=64, 3-stage cp.async pipeline, staging INTERLEAVED into the
// ks compute loop (2 cp.async per ks step) to smooth MIO issue bursts.
// Block 128x128, 256 threads (8 warps 4m x 2n), warp tile 32x64.
// Rows padded to 72 halfs (144B): LDSM + cp.async conflict-free.
// MODE 0: A=g_Ah, B=g_Wh, scatter fp16 to g_Q/g_K/g_V (Q scaled by 0.125*log2e).
// MODE 1: A=g_Xh, B=g_Wph, out = C + bias (fp32).
// ---------------------------------------------------------------------------
template <int MODE>
__global__ void __launch_bounds__(256, 2) gemm_h(const float* __restrict__ bias,
                                                 float* __restrict__ out)
{
    constexpr int KDIM = (MODE == 0) ? 3072 : 1024;
    constexpr int NK   = KDIM / 64;
    constexpr int TILE_BYTES  = 128 * 144;        // 18432 per matrix
    constexpr int STAGE_BYTES = 2 * TILE_BYTES;   // 36864

    extern __shared__ __align__(16) char sm[];
    const uint32_t sbase = smem_u32(sm);

    const __half* __restrict__ A = (MODE == 0) ? g_Ah : g_Xh;
    const __half* __restrict__ B = (MODE == 0) ? g_Wh : g_Wph;

    const int tid  = threadIdx.x;
    const int lane = tid & 31;
    const int w    = tid >> 5;
    const int gid  = lane >> 2;
    const int tig  = lane & 3;
    const int warp_m = (w >> 1) * 32;
    const int warp_n = (w & 1) * 64;
    const int mBase  = blockIdx.y * 128;
    const int nBase  = blockIdx.x * 128;

    const int row_in = lane & 7;
    const int sel    = lane >> 3;
    const int a_row_off = (sel & 1) * 8 + row_in;
    const int a_k_off   = (sel >> 1) * 8;
    const int b_row_off = (sel >> 1) * 8 + row_in;
    const int b_k_off   = (sel & 1) * 8;

    // Issue 2 of the 8 per-tile cp.asyncs (part = 0..3).
    auto stage_part = [&](int kt, int st, int part) {
#pragma unroll
        for (int j = 0; j < 2; j++) {
            const int i   = part * 2 + j;
            const int c   = tid + 256 * i;       // 0..2047
            const int mat = c >> 10;             // 0=A, 1=B
            const int cc  = c & 1023;
            const int row = cc >> 3;
            const int ch  = cc & 7;
            const __half* src = (mat == 0)
                ? (A + (size_t)(mBase + row) * KDIM + kt * 64 + ch * 8)
                : (B + (size_t)(nBase + row) * KDIM + kt * 64 + ch * 8);
            const uint32_t dst = sbase + st * STAGE_BYTES + mat * TILE_BYTES
                               + row * 144 + ch * 16;
            CP_ASYNC16(dst, src);
        }
    };
    auto stage_full = [&](int kt, int st) {
#pragma unroll
        for (int p = 0; p < 4; p++) stage_part(kt, st, p);
        CP_COMMIT();
    };

    float acc[2][8][4];
#pragma unroll
    for (int i = 0; i < 2; i++)
#pragma unroll
        for (int j = 0; j < 8; j++)
#pragma unroll
            for (int e = 0; e < 4; e++) acc[i][j][e] = 0.f;

    stage_full(0, 0);
    stage_full(1, 1);

    for (int kt = 0; kt < NK; kt++) {
        const int st = kt % 3;
        if (kt + 1 < NK) { CP_WAIT1(); } else { CP_WAIT0(); }
        __syncthreads();
        const bool pf = (kt + 2 < NK);
        const int pf_st = (kt + 2) % 3;

        const uint32_t a_sm = sbase + st * STAGE_BYTES;
        const uint32_t b_sm = a_sm + TILE_BYTES;

#pragma unroll
        for (int ks = 0; ks < 4; ks++) {
            if (pf) stage_part(kt + 2, pf_st, ks);   // 2 cp.async per ks step

            uint32_t a[2][4], b[8][2];
#pragma unroll
            for (int mt = 0; mt < 2; mt++) {
                const uint32_t addr = a_sm +
                    (warp_m + mt * 16 + a_row_off) * 144 + (ks * 16 + a_k_off) * 2;
                LDSM_X4(a[mt][0], a[mt][1], a[mt][2], a[mt][3], addr);
            }
#pragma unroll
            for (int pr = 0; pr < 4; pr++) {
                const uint32_t addr = b_sm +
                    (warp_n + pr * 16 + b_row_off) * 144 + (ks * 16 + b_k_off) * 2;
                LDSM_X4(b[2 * pr][0], b[2 * pr][1], b[2 * pr + 1][0], b[2 * pr + 1][1], addr);
            }
#pragma unroll
            for (int mt = 0; mt < 2; mt++)
#pragma unroll
                for (int nt = 0; nt < 8; nt++)
                    mma16(acc[mt][nt], a[mt], b[nt]);
        }
        if (pf) CP_COMMIT();
    }

    // Epilogue. C frag: c0(row g, col 2t), c1(g, 2t+1), c2(g+8, 2t), c3(g+8, 2t+1).
#pragma unroll
    for (int mt = 0; mt < 2; mt++) {
        const int row0 = mBase + warp_m + mt * 16 + gid;
#pragma unroll
        for (int nt = 0; nt < 8; nt++) {
            const int col = nBase + warp_n + nt * 8 + 2 * tig;
            if (MODE == 0) {
                const int t = col >> 10, hh = (col >> 6) & 15, d = col & 63;
                // Q pre-scale folds softmax scale AND log2(e) for exp2-softmax.
                const float sc = (t == 0) ? 0.125f * 1.44269504f : 1.f;
                __half* dst = ((t == 0) ? g_Q : ((t == 1) ? g_K : g_V)) +
                    ((size_t)((row0 >> 11) * 16 + hh) * 2048 + (row0 & 2047)) * 64 + d;
                *(__half2*)dst =
                    __floats2half2_rn(acc[mt][nt][0] * sc, acc[mt][nt][1] * sc);
                *(__half2*)(dst + 8 * 64) =
                    __floats2half2_rn(acc[mt][nt][2] * sc, acc[mt][nt][3] * sc);
            } else {
                const float b0 = bias[col], b1 = bias[col + 1];
                *(float2*)(out + (size_t)row0 * 1024 + col) =
                    make_float2(acc[mt][nt][0] + b0, acc[mt][nt][1] + b1);
                *(float2*)(out + (size_t)(row0 + 8) * 1024 + col) =
                    make_float2(acc[mt][nt][2] + b0, acc[mt][nt][3] + b1);
            }
        }
    }
}

// ---------------------------------------------------------------------------
// fp16 flash attention, fp16x2 exp2 + tensor-pipe denominator (ones-MMA),
// staging interleaved into the S-ks loop (1 cp.async per ks step).
// grid (16, 32), 256 threads, 3-stage cp.async.
// ---------------------------------------------------------------------------
__global__ void __launch_bounds__(256, 2) attn_flash_h()
{
    constexpr int KV_BYTES = 9216;       // 64 rows x 72 halfs (144B)
    constexpr int STAGE_BYTES = 2 * KV_BYTES;
    extern __shared__ __align__(16) char sm[];
    const uint32_t sbase = smem_u32(sm);

    const int bh    = blockIdx.y;
    const int qbase = blockIdx.x * 128;
    const int tid   = threadIdx.x;
    const int lane  = tid & 31;
    const int w     = tid >> 5;
    const int gid   = lane >> 2;
    const int tig   = lane & 3;

    const int row_in = lane & 7;
    const int sel    = lane >> 3;
    const int b_row_off = (sel >> 1) * 8 + row_in;
    const int b_k_off   = (sel & 1) * 8;
    const int v_krow_off = (sel & 1) * 8 + row_in;
    const int v_ncol_off = (sel >> 1) * 16;

    const __half* Kp = g_K + (size_t)bh * (2048 * 64);
    const __half* Vp = g_V + (size_t)bh * (2048 * 64);

    auto stage_part = [&](int kv_tile, int st, int i) {
        const int c   = tid + 256 * i;
        const int mat = c >> 9;          // 0=K, 1=V
        const int cc  = c & 511;
        const int row = cc >> 3;
        const int ch  = cc & 7;
        const __half* src = ((mat == 0) ? Kp : Vp) +
            (size_t)(kv_tile * 64 + row) * 64 + ch * 8;
        const uint32_t dst = sbase + st * STAGE_BYTES + mat * KV_BYTES + row * 144 + ch * 16;
        CP_ASYNC16(dst, src);
    };
    auto stage_full = [&](int kv_tile, int st) {
#pragma unroll
        for (int i = 0; i < 4; i++) stage_part(kv_tile, st, i);
        CP_COMMIT();
    };

    uint32_t qa[4][4];
    {
        const __half* q0 = g_Q + ((size_t)bh * 2048 + qbase + w * 16 + gid) * 64;
#pragma unroll
        for (int s = 0; s < 4; s++) {
            qa[s][0] = *(const uint32_t*)(q0 + s * 16 + 2 * tig);
            qa[s][1] = *(const uint32_t*)(q0 + 8 * 64 + s * 16 + 2 * tig);
            qa[s][2] = *(const uint32_t*)(q0 + s * 16 + 2 * tig + 8);
            qa[s][3] = *(const uint32_t*)(q0 + 8 * 64 + s * 16 + 2 * tig + 8);
        }
    }

    float o[8][4];
#pragma unroll
    for (int i = 0; i < 8; i++)
#pragma unroll
        for (int j = 0; j < 4; j++) o[i][j] = 0.f;

    // Denominator accumulator via ones-MMA: c0/c1 = row gid sum, c2/c3 = row gid+8.
    float l_acc[4] = {0.f, 0.f, 0.f, 0.f};
    const uint32_t ones2 = pack_h2(1.f, 1.f);
    const uint32_t ones_b[2] = {ones2, ones2};

    stage_full(0, 0);
    stage_full(1, 1);

    for (int it = 0; it < 32; it++) {
        const int st = it % 3;
        if (it + 1 < 32) { CP_WAIT1(); } else { CP_WAIT0(); }
        __syncthreads();
        const bool pf = (it + 2 < 32);
        const int pf_st = (it + 2) % 3;

        const uint32_t ksb = sbase + st * STAGE_BYTES;
        const uint32_t vsb = ksb + KV_BYTES;

        // S = Q K^T (base-2 domain: log2e pre-folded into Q)
        float s[8][4];
#pragma unroll
        for (int i = 0; i < 8; i++)
#pragma unroll
            for (int j = 0; j < 4; j++) s[i][j] = 0.f;
#pragma unroll
        for (int ks = 0; ks < 4; ks++) {
            if (pf) stage_part(it + 2, pf_st, ks);   // 1 cp.async per ks step

            uint32_t b[8][2];
#pragma unroll
            for (int pr = 0; pr < 4; pr++) {
                const uint32_t addr = ksb +
                    (pr * 16 + b_row_off) * 144 + (ks * 16 + b_k_off) * 2;
                LDSM_X4(b[2 * pr][0], b[2 * pr][1], b[2 * pr + 1][0], b[2 * pr + 1][1], addr);
            }
#pragma unroll
            for (int nt = 0; nt < 8; nt++)
                mma16(s[nt], qa[ks], b[nt]);
        }
        if (pf) CP_COMMIT();

        // P = exp2(S) in fp16x2; l via ones-MMA; O += P V.
#pragma unroll
        for (int kt = 0; kt < 4; kt++) {
            uint32_t pa[4];
            pa[0] = pack_h2(s[2 * kt][0],     s[2 * kt][1]);
            pa[1] = pack_h2(s[2 * kt][2],     s[2 * kt][3]);
            pa[2] = pack_h2(s[2 * kt + 1][0], s[2 * kt + 1][1]);
            pa[3] = pack_h2(s[2 * kt + 1][2], s[2 * kt + 1][3]);
            EX2_H2(pa[0]);
            EX2_H2(pa[1]);
            EX2_H2(pa[2]);
            EX2_H2(pa[3]);

            mma16(l_acc, pa, ones_b);   // row sums on the tensor pipe

#pragma unroll
            for (int pr = 0; pr < 4; pr++) {
                const uint32_t addr = vsb +
                    (kt * 16 + v_krow_off) * 144 + pr * 32 + v_ncol_off;
                uint32_t b[4];
                LDSM_X4_TRANS(b[0], b[1], b[2], b[3], addr);
                mma16(o[2 * pr],     pa, b);
                mma16(o[2 * pr + 1], pa, b + 2);
            }
        }
    }

    // l_acc already holds full row sums in every lane (ones-MMA reduces k).
    const float inv0 = 1.f / l_acc[0], inv1 = 1.f / l_acc[2];
    const int b = bh >> 4, h = bh & 15;
    const int n0 = qbase + w * 16 + gid;
    __half* x0 = g_Xh + ((size_t)b * 2048 + n0) * 1024 + h * 64;
    __half* x8 = x0 + 8 * 1024;
#pragma unroll
    for (int nt = 0; nt < 8; nt++) {
        const int d = nt * 8 + 2 * tig;
        *(__half2*)(x0 + d) = __floats2half2_rn(o[nt][0] * inv0, o[nt][1] * inv0);
        *(__half2*)(x8 + d) = __floats2half2_rn(o[nt][2] * inv1, o[nt][3] * inv1);
    }
}

// ---------------------------------------------------------------------------
extern "C" void kernel_launch(void* const* d_in, const int* in_sizes, int n_in,
                              void* d_out, int out_size)
{
    const float* q     = (const float*)d_in[0];
    const float* k     = (const float*)d_in[1];
    const float* v     = (const float*)d_in[2];
    const float* Wqkv  = (const float*)d_in[3];
    const float* Wproj = (const float*)d_in[4];
    const float* bproj = (const float*)d_in[5];
    float* out = (float*)d_out;

    static bool attr_done = false;
    const int GEMM_SMEM = 3 * 36864;   // 110592 (3-stage, BK=64); 2 CTAs = 221KB
    const int ATTN_SMEM = 3 * 18432;   // 55296
    if (!attr_done) {
        cudaFuncSetAttribute(gemm_h<0>, cudaFuncAttributeMaxDynamicSharedMemorySize, GEMM_SMEM);
        cudaFuncSetAttribute(gemm_h<1>, cudaFuncAttributeMaxDynamicSharedMemorySize, GEMM_SMEM);
        cudaFuncSetAttribute(attn_flash_h, cudaFuncAttributeMaxDynamicSharedMemorySize, ATTN_SMEM);
        attr_done = true;
    }

    // 0) merged, vectorized fp32 -> fp16 prepass
    cvt_all<<<2048, 256>>>(q, k, v, Wqkv, Wproj);
    // 1) fused QKV projection -> g_Q/g_K/g_V (fp16, Q pre-scaled incl. log2e)
    gemm_h<0><<<dim3(24, 32), 256, GEMM_SMEM>>>(nullptr, nullptr);
    // 2) flash attention -> g_Xh (fp16)
    attn_flash_h<<<dim3(16, 32), 256, ATTN_SMEM>>>();
    // 3) output projection + bias -> d_out (fp32)
    gemm_h<1><<<dim3(8, 32), 256, GEMM_SMEM>>>(bproj, out);
}